// round 16
// baseline (speedup 1.0000x reference)
#include <cuda_runtime.h>

#define T_STEPS 500
#define NB 4096
#define ROWS 28          // rows per CTA (with overlap; 148*28 >= 4096)
#define HR   14          // half rows
#define NCTA 148
#define NTHR 256

typedef unsigned long long ull;

// packed fp32x2 FMA (sm_103a FFMA2)
__device__ __forceinline__ ull ffma2(ull a, ull b, ull c) {
    ull d;
    asm("fma.rn.f32x2 %0, %1, %2, %3;" : "=l"(d) : "l"(a), "l"(b), "l"(c));
    return d;
}
__device__ __forceinline__ float pair_sum(ull p) {
    return __uint_as_float((unsigned)p) + __uint_as_float((unsigned)(p >> 32));
}
__device__ __forceinline__ ull packf2(float lo, float hi) {
    return (ull)__float_as_uint(lo) | ((ull)__float_as_uint(hi) << 32);
}
__device__ __forceinline__ void bar_named(int id) {
    asm volatile("bar.sync %0, %1;" :: "r"(id), "r"(128) : "memory");
}

// SMEM: w1pk[2][16][128] ull; floats hsm[2][28][132], pp[2][4][28][40],
// ys[28][32], b2s[64]. (hsm 132 / pp 40 padding: all GEMM2 accesses
// single-phase — see R12 derivation)
#define W1PK_U (2*16*128)                 // 4096 ull = 32 KB
#define HS   132
#define PPS  40
#define HSM_F  (2*ROWS*HS)                // 7392
#define PP_F   (2*4*ROWS*PPS)             // 8960
#define YS_F   (ROWS*32)                  // 896
#define SMEM_BYTES (W1PK_U*8 + (HSM_F + PP_F + YS_F + 64)*4)  // 102,016 B

__global__ __launch_bounds__(NTHR, 1)
void nsde12(const float* __restrict__ y0, const float* __restrict__ noise,
            const float* __restrict__ dw1, const float* __restrict__ db1,
            const float* __restrict__ dw2, const float* __restrict__ db2,
            const float* __restrict__ gw1, const float* __restrict__ gb1,
            const float* __restrict__ gw2, const float* __restrict__ gb2,
            float* __restrict__ out)
{
    extern __shared__ char smraw[];
    ull*   w1pk = (ull*)smraw;              // [m][kp][j]
    float* hsm  = (float*)(w1pk + W1PK_U);  // [m][r][HS]
    float* pp   = hsm + HSM_F;              // [m][q][r][PPS]
    float* ys   = pp  + PP_F;               // [r][32]
    float* b2s  = ys  + YS_F;               // [2][32]

    const int tid  = threadIdx.x;
    const int lane = tid & 31;
    const int wid  = tid >> 5;
    const int m    = wid >> 2;              // 0 drift, 1 diffusion
    // overlapping base: floor(bid*4068/147); full coverage, dup rows
    // recompute identical values (deterministic duplicate writes)
    const int base = (int)(((long long)blockIdx.x * (NB - ROWS)) / (NCTA - 1));

    // GEMM1 role: j-half + row-half (row half == wid&1, shared with epilogue)
    const int hj   = (wid >> 1) & 1;
    const int half = wid & 1;               // 0 -> rows 0-13, 1 -> rows 14-27
    const int rb1  = half * HR;
    const int j0   = hj * 64 + lane;
    const int j1   = j0 + 32;

    // GEMM2 role: j-quarter; lane -> outputs il, il+16; half-warp -> r-half
    const int q   = wid & 3;
    const int il  = lane & 15;
    const int rb2 = (lane >> 4) * HR;

    // Epilogue role: warp's row-half matches its G1 row-half
    const int slot = (wid >> 1) * 32 + lane;        // 0..127
    const bool eact = slot < HR * 8;                // 112 active per half
    const int v4 = half * (HR * 32) + slot * 4;

    // ---- stage W1 into SMEM as k-packed f32x2 ----
    for (int idx = tid; idx < W1PK_U; idx += NTHR) {
        int mm = idx >> 11, rest = idx & 2047;
        int kp = rest >> 7, j = rest & 127;
        const float* W = mm ? gw1 : dw1;
        w1pk[idx] = packf2(W[j * 32 + 2 * kp], W[j * 32 + 2 * kp + 1]);
    }
    // ---- W2 rows (i = il, il+16) for this quarter -> registers ----
    const float* W2 = m ? gw2 : dw2;
    ull w2p0[16], w2p1[16];
    #pragma unroll
    for (int t = 0; t < 8; t++) {
        double2 u0 = *(const double2*)(W2 + il * 128 + q * 32 + t * 4);
        w2p0[2*t]   = __double_as_longlong(u0.x);
        w2p0[2*t+1] = __double_as_longlong(u0.y);
        double2 u1 = *(const double2*)(W2 + (il + 16) * 128 + q * 32 + t * 4);
        w2p1[2*t]   = __double_as_longlong(u1.x);
        w2p1[2*t+1] = __double_as_longlong(u1.y);
    }
    const float* B1 = m ? gb1 : db1;
    const float b1_0 = B1[j0], b1_1 = B1[j1];
    if (tid < 64) b2s[tid] = (tid < 32) ? db2[tid] : gb2[tid - 32];

    // ---- init ys + out[0] (epilogue mapping) ----
    if (eact) {
        float4 val = *(const float4*)(y0 + (size_t)base * 32 + v4);
        *(float4*)(ys + v4) = val;
        *(float4*)(out + (size_t)base * 32 + v4) = val;
    }
    __syncthreads();

    const float dt   = 0.01f;
    const float sqdt = __fsqrt_rn(dt);
    const ull*   w1b = w1pk + m * 2048;
    float*       hwb = hsm + m * (ROWS * HS);
    const float* hq  = hsm + m * (ROWS * HS) + q * 32;
    float*       ppb = pp + (m * 4 + q) * (ROWS * PPS);

    // k4 = 0,1 weights cached in registers (loop-invariant): kills the
    // post-barrier LDS bubble at G1's head and 16 wf/warp/step
    const ull wA0 = w1b[0 * 128 + j0], wA1 = w1b[1 * 128 + j0];
    const ull wA2 = w1b[2 * 128 + j0], wA3 = w1b[3 * 128 + j0];
    const ull wB0 = w1b[0 * 128 + j1], wB1 = w1b[1 * 128 + j1];
    const ull wB2 = w1b[2 * 128 + j1], wB3 = w1b[3 * 128 + j1];

    for (int s = 0; s < T_STEPS; s++) {
        // prefetch step noise (epilogue mapping)
        float4 nv;
        if (eact)
            nv = *(const float4*)(noise + ((size_t)s * NB + base) * 32 + v4);

        // ---- GEMM1: h[r][j0/j1] over HR rows; 1 y-load -> 4 ffma2 ----
        ull acc0[HR], acc1[HR];
        #pragma unroll
        for (int r = 0; r < HR; r++) {
            double2 yv = *(const double2*)(ys + (rb1 + r) * 32);
            ull ylo = __double_as_longlong(yv.x);
            ull yhi = __double_as_longlong(yv.y);
            ull a = ffma2(wA0, ylo, (ull)__float_as_uint(b1_0));
            a = ffma2(wA1, yhi, a);
            ull b = ffma2(wB0, ylo, (ull)__float_as_uint(b1_1));
            b = ffma2(wB1, yhi, b);
            acc0[r] = a; acc1[r] = b;
        }
        #pragma unroll
        for (int r = 0; r < HR; r++) {
            double2 yv = *(const double2*)(ys + (rb1 + r) * 32 + 4);
            ull ylo = __double_as_longlong(yv.x);
            ull yhi = __double_as_longlong(yv.y);
            acc0[r] = ffma2(wA2, ylo, acc0[r]);
            acc0[r] = ffma2(wA3, yhi, acc0[r]);
            acc1[r] = ffma2(wB2, ylo, acc1[r]);
            acc1[r] = ffma2(wB3, yhi, acc1[r]);
        }
        #pragma unroll
        for (int k4 = 2; k4 < 8; k4++) {
            ull w00 = w1b[(2*k4)   * 128 + j0];
            ull w01 = w1b[(2*k4+1) * 128 + j0];
            ull w10 = w1b[(2*k4)   * 128 + j1];
            ull w11 = w1b[(2*k4+1) * 128 + j1];
            #pragma unroll
            for (int r = 0; r < HR; r++) {
                double2 yv = *(const double2*)(ys + (rb1 + r) * 32 + k4 * 4);
                ull ylo = __double_as_longlong(yv.x);
                ull yhi = __double_as_longlong(yv.y);
                acc0[r] = ffma2(w00, ylo, acc0[r]);
                acc0[r] = ffma2(w01, yhi, acc0[r]);
                acc1[r] = ffma2(w10, ylo, acc1[r]);
                acc1[r] = ffma2(w11, yhi, acc1[r]);
            }
        }
        #pragma unroll
        for (int r = 0; r < HR; r++) {
            hwb[(rb1 + r) * HS + j0] = fmaxf(pair_sum(acc0[r]), 0.0f);
            hwb[(rb1 + r) * HS + j1] = fmaxf(pair_sum(acc1[r]), 0.0f);
        }
        // h[m] produced and consumed within MLP group m (warps 4m..4m+3)
        bar_named(1 + m);

        // ---- GEMM2: partial[r][il/il+16] over HR rows; 1 h-load -> 4 ffma2 ----
        ull a0[HR], a1[HR];
        #pragma unroll
        for (int r = 0; r < HR; r++) { a0[r] = 0ull; a1[r] = 0ull; }
        const float* hrow = hq + rb2 * HS;
        #pragma unroll
        for (int j4 = 0; j4 < 8; j4++) {
            #pragma unroll
            for (int r = 0; r < HR; r++) {
                double2 hv = *(const double2*)(hrow + r * HS + j4 * 4);
                ull hlo = __double_as_longlong(hv.x);
                ull hhi = __double_as_longlong(hv.y);
                a0[r] = ffma2(w2p0[2*j4],   hlo, a0[r]);
                a0[r] = ffma2(w2p0[2*j4+1], hhi, a0[r]);
                a1[r] = ffma2(w2p1[2*j4],   hlo, a1[r]);
                a1[r] = ffma2(w2p1[2*j4+1], hhi, a1[r]);
            }
        }
        #pragma unroll
        for (int r = 0; r < HR; r++) {
            ppb[(rb2 + r) * PPS + il]      = pair_sum(a0[r]);
            ppb[(rb2 + r) * PPS + il + 16] = pair_sum(a1[r]);
        }
        __syncthreads();   // pp written by all 8 warps -> full barrier

        // ---- reduce quarters + Euler–Maruyama; warp's own row-half only ----
        if (eact) {
            int r = v4 >> 5, i = v4 & 31;
            const float* p = pp + r * PPS + i;
            float4 pa = *(const float4*)(p);
            float4 pb = *(const float4*)(p + ROWS*PPS);
            float4 pc = *(const float4*)(p + 2*ROWS*PPS);
            float4 pd = *(const float4*)(p + 3*ROWS*PPS);
            float4 bv = *(const float4*)(b2s + i);
            float fx = pa.x + pb.x + pc.x + pd.x + bv.x;
            float fy = pa.y + pb.y + pc.y + pd.y + bv.y;
            float fz = pa.z + pb.z + pc.z + pd.z + bv.z;
            float fw = pa.w + pb.w + pc.w + pd.w + bv.w;
            const float* pg = p + 4*ROWS*PPS;
            float4 ga = *(const float4*)(pg);
            float4 gb = *(const float4*)(pg + ROWS*PPS);
            float4 gc = *(const float4*)(pg + 2*ROWS*PPS);
            float4 gd = *(const float4*)(pg + 3*ROWS*PPS);
            float4 bg = *(const float4*)(b2s + 32 + i);
            float gx = ga.x + gb.x + gc.x + gd.x + bg.x;
            float gy = ga.y + gb.y + gc.y + gd.y + bg.y;
            float gz = ga.z + gb.z + gc.z + gd.z + bg.z;
            float gw = ga.w + gb.w + gc.w + gd.w + bg.w;
            float4 yv = *(const float4*)(ys + v4);
            float4 z;
            z.x = fmaf(gx, sqdt * nv.x, fmaf(fx, dt, yv.x));
            z.y = fmaf(gy, sqdt * nv.y, fmaf(fy, dt, yv.y));
            z.z = fmaf(gz, sqdt * nv.z, fmaf(fz, dt, yv.z));
            z.w = fmaf(gw, sqdt * nv.w, fmaf(fw, dt, yv.w));
            *(float4*)(out + ((size_t)(s + 1) * NB + base) * 32 + v4) = z;
            *(float4*)(ys + v4) = z;   // rewrites exactly what it read
        }
        // row-half barrier only: even warps (rows 0-13) and odd warps
        // (rows 14-27) desync — next G1 half starts while the other half's
        // epilogue drains. ys is strictly half-local; pp reuse is ordered
        // via (this bar -> G1 -> group bar -> G2).
        bar_named(3 + half);
    }
}

extern "C" void kernel_launch(void* const* d_in, const int* in_sizes, int n_in,
                              void* d_out, int out_size)
{
    // metadata order: ts, y0, noise, drift_w1, drift_b1, drift_w2, drift_b2,
    //                 diff_w1, diff_b1, diff_w2, diff_b2
    const float* y0    = (const float*)d_in[1];
    const float* noise = (const float*)d_in[2];
    const float* dw1   = (const float*)d_in[3];
    const float* db1   = (const float*)d_in[4];
    const float* dw2   = (const float*)d_in[5];
    const float* db2   = (const float*)d_in[6];
    const float* gw1   = (const float*)d_in[7];
    const float* gb1   = (const float*)d_in[8];
    const float* gw2   = (const float*)d_in[9];
    const float* gb2   = (const float*)d_in[10];
    float* out = (float*)d_out;

    cudaFuncSetAttribute(nsde12,
                         cudaFuncAttributeMaxDynamicSharedMemorySize,
                         SMEM_BYTES);
    nsde12<<<NCTA, NTHR, SMEM_BYTES>>>(y0, noise, dw1, db1, dw2, db2,
                                       gw1, gb1, gw2, gb2, out);
}